// round 13
// baseline (speedup 1.0000x reference)
#include <cuda_runtime.h>
#include <cstdint>
#include <math.h>

#define B_DIM 2
#define H_DIM 16
#define S_DIM 2048
#define E_DIM 1024
#define XROWS 4096            // B*S
#define KPAIRS 512            // 1024/2

// ---- device scratch (allocation-free rule) ----
__device__ float g_V [B_DIM*H_DIM*S_DIM*64];          // [bh][s][d] fp32
#define QP_COMP (B_DIM*H_DIM*S_DIM*32)
__device__ uint32_t g_Qp[3*QP_COMP];                  // packed Q h/m/l
__device__ uint32_t g_Kp[3*QP_COMP];
#define XC  (KPAIRS*XROWS)
__device__ uint32_t g_xp [3*XC];                      // x split h/m/l
#define WQC (KPAIRS*3*E_DIM)
__device__ uint32_t g_qwp[3*WQC];                     // qkv_w h/m/l
#define OWC (KPAIRS*E_DIM)
__device__ uint32_t g_owp[2*OWC];                     // out_w h/m
#define AVC (KPAIRS*XROWS)
__device__ uint32_t g_avp[2*AVC];                     // AV h/m (written by attn)
// Precomputed RNG: uf = (float)(threefry_bits(idx) >> 9), one per attn element
#define RNG_N 134217728                                // 2^27
__device__ float g_rng[RNG_N];                         // 512MB

// ===========================================================================
// bf16 helpers
// ===========================================================================
__device__ __forceinline__ uint32_t pack_bf16(float lo, float hi) {
  uint32_t r;
  asm("cvt.rn.satfinite.bf16x2.f32 %0, %1, %2;" : "=r"(r) : "f"(hi), "f"(lo));
  return r;
}
__device__ __forceinline__ float lo_f(uint32_t u) { return __uint_as_float(u << 16); }
__device__ __forceinline__ float hi_f(uint32_t u) { return __uint_as_float(u & 0xFFFF0000u); }
__device__ __forceinline__ void split3(float fe, float fo,
                                       uint32_t& h, uint32_t& m, uint32_t& l) {
  h = pack_bf16(fe, fo);
  float re = fe - lo_f(h);
  float ro = fo - hi_f(h);
  m = pack_bf16(re, ro);
  l = pack_bf16(re - lo_f(m), ro - hi_f(m));
}
__device__ __forceinline__ void mma_bf16(float* c, const uint32_t* a,
                                         uint32_t b0, uint32_t b1) {
  asm volatile(
      "mma.sync.aligned.m16n8k16.row.col.f32.bf16.bf16.f32 "
      "{%0,%1,%2,%3},{%4,%5,%6,%7},{%8,%9},{%0,%1,%2,%3};"
      : "+f"(c[0]), "+f"(c[1]), "+f"(c[2]), "+f"(c[3])
      : "r"(a[0]), "r"(a[1]), "r"(a[2]), "r"(a[3]), "r"(b0), "r"(b1));
}

// ===========================================================================
// JAX partitionable-threefry, key (0,42)
// ===========================================================================
__device__ __forceinline__ uint32_t jax_bits_k42(uint32_t idx) {
  const uint32_t ks0 = 0u;
  const uint32_t ks1 = 42u;
  const uint32_t ks2 = 42u ^ 0x1BD11BDAu;
  uint32_t x0 = ks0;
  uint32_t x1 = idx + ks1;
#define TF_ROUND(r) { x0 += x1; x1 = __funnelshift_l(x1, x1, (r)); x1 ^= x0; }
  TF_ROUND(13) TF_ROUND(15) TF_ROUND(26) TF_ROUND(6)
  x0 += ks1; x1 += ks2 + 1u;
  TF_ROUND(17) TF_ROUND(29) TF_ROUND(16) TF_ROUND(24)
  x0 += ks2; x1 += ks0 + 2u;
  TF_ROUND(13) TF_ROUND(15) TF_ROUND(26) TF_ROUND(6)
  x0 += ks0; x1 += ks1 + 3u;
  TF_ROUND(17) TF_ROUND(29) TF_ROUND(16) TF_ROUND(24)
  x0 += ks1; x1 += ks2 + 4u;
  TF_ROUND(13) TF_ROUND(15) TF_ROUND(26) TF_ROUND(6)
  x0 += ks2; x1 += ks0 + 5u;
#undef TF_ROUND
  return x0 ^ x1;
}

// ===========================================================================
// presplit: src [rows][1024] fp32 -> dst [NC][kpair][rows] packed bf16x2
// ===========================================================================
template<int NC>
__global__ void presplit(const float* __restrict__ src,
                         uint32_t* __restrict__ dst, int nrows) {
  const int row = blockIdx.x*256 + threadIdx.x;
  const int kp  = blockIdx.y;
  float2 v = *(const float2*)(src + (size_t)row*1024 + 2*kp);
  uint32_t h, m, l;
  split3(v.x, v.y, h, m, l);
  const size_t C = (size_t)KPAIRS * nrows;
  const size_t base = (size_t)kp*nrows + row;
  dst[base] = h;
  dst[base + C] = m;
  if (NC == 3) dst[base + 2*C] = l;
}

// ===========================================================================
// qkv GEMM from pre-split operands + FUSED RNG production.
// Per k-iteration each thread also computes RNGN threefry elements
// (idle-ALU-pipe work overlapping the tensor stream).
// SIX=1: x6, RNGN=6 (384/thr, CTAs 0..1023 cover elements [0, 100663296)).
// SIX=0: x3, RNGN=4 (256/thr, CTAs cover [100663296, 2^27)).
// ===========================================================================
template<int SIX>
__global__ void __launch_bounds__(256, 2)
qkv_tc(const uint32_t* __restrict__ Apk, const uint32_t* __restrict__ Wpk,
       const float* __restrict__ bias, int ncol0) {
  const int NC   = SIX ? 3 : 2;
  const int RNGN = SIX ? 6 : 4;
  __shared__ uint32_t As[2][3*8*136];
  __shared__ uint32_t Ws[2][3*8*72];
  const int tid  = threadIdx.x;
  const int lane = tid & 31;
  const int warp = tid >> 5;
  const int g    = lane >> 2;
  const int tg   = lane & 3;
  const int wm   = warp & 3;
  const int wn   = warp >> 2;
  const int m0   = blockIdx.y << 7;
  const int n0   = blockIdx.x << 6;

  // RNG chunk base for this CTA
  const uint32_t bid = blockIdx.y * gridDim.x + blockIdx.x;
  const uint32_t rngbase = SIX ? (bid * 98304u)
                               : (100663296u + bid * 65536u);

  const int akp = tid >> 5;
  const int ar4 = lane * 4;
  const int wkp = (tid >> 4) & 7;
  const int wc4 = (tid & 15) * 4;
  const bool wact = tid < 128;

  float acc[2][4][4], c[2][4][4];
#pragma unroll
  for (int mt = 0; mt < 2; mt++)
#pragma unroll
    for (int nt = 0; nt < 4; nt++)
#pragma unroll
      for (int r = 0; r < 4; r++) { acc[mt][nt][r] = 0.0f; c[mt][nt][r] = 0.0f; }

#pragma unroll
  for (int cc = 0; cc < NC; cc++) {
    uint4 a = *(const uint4*)(Apk + (size_t)cc*XC + (size_t)akp*XROWS + m0 + ar4);
    *(uint4*)&As[0][(cc*8 + akp)*136 + ar4] = a;
    if (wact) {
      uint4 w = *(const uint4*)(Wpk + (size_t)cc*WQC + (size_t)wkp*(3*E_DIM) + ncol0 + n0 + wc4);
      *(uint4*)&Ws[0][(cc*8 + wkp)*72 + wc4] = w;
    }
  }
  __syncthreads();

  uint4 av[3], wv[3];
  for (int it = 0; it < 64; it++) {
    const int buf = it & 1;
    if (it + 1 < 64) {
#pragma unroll
      for (int cc = 0; cc < NC; cc++) {
        av[cc] = *(const uint4*)(Apk + (size_t)cc*XC +
                                 (size_t)((it+1)*8 + akp)*XROWS + m0 + ar4);
        if (wact)
          wv[cc] = *(const uint4*)(Wpk + (size_t)cc*WQC +
                                   (size_t)((it+1)*8 + wkp)*(3*E_DIM) + ncol0 + n0 + wc4);
      }
    }

    uint32_t Ah[2][4], Am[2][4], Al[2][4];
#pragma unroll
    for (int mt = 0; mt < 2; mt++) {
      const int r0 = wm*32 + mt*16 + g;
#pragma unroll
      for (int p = 0; p < 4; p++) {
        const int kp = tg + ((p & 2) ? 4 : 0);
        const int rr = r0 + ((p & 1) ? 8 : 0);
        Ah[mt][p] = As[buf][(0*8 + kp)*136 + rr];
        Am[mt][p] = As[buf][(1*8 + kp)*136 + rr];
        if (SIX) Al[mt][p] = As[buf][(2*8 + kp)*136 + rr];
      }
    }

#pragma unroll
    for (int nt = 0; nt < 4; nt++) {
      const int n = wn*32 + nt*8 + g;
      uint32_t Bh0 = Ws[buf][(0*8 + tg  )*72 + n];
      uint32_t Bh1 = Ws[buf][(0*8 + tg+4)*72 + n];
      uint32_t Bm0 = Ws[buf][(1*8 + tg  )*72 + n];
      uint32_t Bm1 = Ws[buf][(1*8 + tg+4)*72 + n];
      uint32_t Bl0 = 0, Bl1 = 0;
      if (SIX) { Bl0 = Ws[buf][(2*8 + tg)*72 + n]; Bl1 = Ws[buf][(2*8 + tg+4)*72 + n]; }
#pragma unroll
      for (int mt = 0; mt < 2; mt++) {
        mma_bf16(c[mt][nt], Ah[mt], Bh0, Bh1);
        mma_bf16(c[mt][nt], Ah[mt], Bm0, Bm1);
        mma_bf16(c[mt][nt], Am[mt], Bh0, Bh1);
        if (SIX) {
          mma_bf16(c[mt][nt], Ah[mt], Bl0, Bl1);
          mma_bf16(c[mt][nt], Am[mt], Bm0, Bm1);
          mma_bf16(c[mt][nt], Al[mt], Bh0, Bh1);
        }
      }
    }

    // ---- fused RNG production (idle ALU slots; coalesced stores) ----
#pragma unroll
    for (int e = 0; e < RNGN; e++) {
      uint32_t idx = rngbase + (uint32_t)((it*RNGN + e)*256 + tid);
      g_rng[idx] = (float)(jax_bits_k42(idx) >> 9);
    }

    if (it + 1 < 64) {
      const int nb = buf ^ 1;
#pragma unroll
      for (int cc = 0; cc < NC; cc++) {
        *(uint4*)&As[nb][(cc*8 + akp)*136 + ar4] = av[cc];
        if (wact) *(uint4*)&Ws[nb][(cc*8 + wkp)*72 + wc4] = wv[cc];
      }
      __syncthreads();
    }

    if ((it & 3) == 3) {
#pragma unroll
      for (int mt = 0; mt < 2; mt++)
#pragma unroll
        for (int nt = 0; nt < 4; nt++)
#pragma unroll
          for (int r = 0; r < 4; r++) {
            acc[mt][nt][r] += c[mt][nt][r];
            c[mt][nt][r] = 0.0f;
          }
    }
  }

  // epilogue (unchanged)
#pragma unroll
  for (int nt = 0; nt < 4; nt++) {
    const int col = ncol0 + n0 + wn*32 + nt*8 + tg*2;
    const float bx = bias[col], by = bias[col+1];
    const int t  = col >> 10;
    const int hh = (col >> 6) & 15;
    const int d0 = col & 63;
#pragma unroll
    for (int mt = 0; mt < 2; mt++) {
      const int row = m0 + wm*32 + mt*16 + g;
      const int bb = row >> 11;
      const int s  = row & 2047;
      if (SIX) {
        uint32_t* dst = (t == 0) ? g_Qp : g_Kp;
        const size_t base = ((size_t)(bb*H_DIM + hh)*S_DIM + s)*32 + (d0 >> 1);
#pragma unroll
        for (int rr = 0; rr < 2; rr++) {
          uint32_t h, m, l;
          split3(acc[mt][nt][rr*2] + bx, acc[mt][nt][rr*2+1] + by, h, m, l);
          size_t idx = base + (size_t)rr*8*32;
          dst[idx]             = h;
          dst[idx + QP_COMP]   = m;
          dst[idx + 2*QP_COMP] = l;
        }
      } else {
        size_t base = ((size_t)(bb*H_DIM + hh)*S_DIM + s)*64 + d0;
        *(float2*)&g_V[base] =
            make_float2(acc[mt][nt][0] + bx, acc[mt][nt][1] + by);
        *(float2*)&g_V[base + 8*64] =
            make_float2(acc[mt][nt][2] + bx, acc[mt][nt][3] + by);
      }
    }
  }
}

// ===========================================================================
// proj GEMM (unchanged from r12)
// ===========================================================================
__global__ void __launch_bounds__(256, 2)
bf16_proj(const uint32_t* __restrict__ Apk, const uint32_t* __restrict__ Wpk,
          const float* __restrict__ bias, float* __restrict__ C) {
  __shared__ uint32_t As[2*8*136];
  __shared__ uint32_t Ws[2*8*136];
  const int tid  = threadIdx.x;
  const int lane = tid & 31;
  const int warp = tid >> 5;
  const int g    = lane >> 2;
  const int tg   = lane & 3;
  const int wm   = warp & 3;
  const int wn   = warp >> 2;
  const int m0   = blockIdx.y << 7;
  const int n0   = blockIdx.x << 7;

  const int kp = tid >> 5;
  const int r4 = lane * 4;

  float c[2][8][4];
#pragma unroll
  for (int mt = 0; mt < 2; mt++)
#pragma unroll
    for (int nt = 0; nt < 8; nt++)
#pragma unroll
      for (int r = 0; r < 4; r++) c[mt][nt][r] = 0.0f;

  uint4 av[2], wv[2];
#pragma unroll
  for (int cc = 0; cc < 2; cc++) {
    av[cc] = *(const uint4*)(Apk + (size_t)cc*AVC + (size_t)kp*XROWS + m0 + r4);
    wv[cc] = *(const uint4*)(Wpk + (size_t)cc*OWC + (size_t)kp*E_DIM + n0 + r4);
  }

  for (int it = 0; it < 64; it++) {
#pragma unroll
    for (int cc = 0; cc < 2; cc++) {
      *(uint4*)&As[(cc*8 + kp)*136 + r4] = av[cc];
      *(uint4*)&Ws[(cc*8 + kp)*136 + r4] = wv[cc];
    }
    __syncthreads();
    if (it + 1 < 64) {
#pragma unroll
      for (int cc = 0; cc < 2; cc++) {
        av[cc] = *(const uint4*)(Apk + (size_t)cc*AVC +
                                 (size_t)((it+1)*8 + kp)*XROWS + m0 + r4);
        wv[cc] = *(const uint4*)(Wpk + (size_t)cc*OWC +
                                 (size_t)((it+1)*8 + kp)*E_DIM + n0 + r4);
      }
    }

    uint32_t Ah[2][4], Am[2][4];
#pragma unroll
    for (int mt = 0; mt < 2; mt++) {
      const int r0 = wm*32 + mt*16 + g;
#pragma unroll
      for (int p = 0; p < 4; p++) {
        const int kq = tg + ((p & 2) ? 4 : 0);
        const int rr = r0 + ((p & 1) ? 8 : 0);
        Ah[mt][p] = As[(0*8 + kq)*136 + rr];
        Am[mt][p] = As[(1*8 + kq)*136 + rr];
      }
    }

#pragma unroll
    for (int nt = 0; nt < 8; nt++) {
      const int n = wn*64 + nt*8 + g;
      uint32_t Bh0 = Ws[(0*8 + tg  )*136 + n];
      uint32_t Bh1 = Ws[(0*8 + tg+4)*136 + n];
      uint32_t Bm0 = Ws[(1*8 + tg  )*136 + n];
      uint32_t Bm1 = Ws[(1*8 + tg+4)*136 + n];
#pragma unroll
      for (int mt = 0; mt < 2; mt++) {
        mma_bf16(c[mt][nt], Ah[mt], Bh0, Bh1);
        mma_bf16(c[mt][nt], Ah[mt], Bm0, Bm1);
        mma_bf16(c[mt][nt], Am[mt], Bh0, Bh1);
      }
    }
    __syncthreads();
  }

#pragma unroll
  for (int nt = 0; nt < 8; nt++) {
    const int col = n0 + wn*64 + nt*8 + tg*2;
    const float bx = bias[col], by = bias[col+1];
#pragma unroll
    for (int mt = 0; mt < 2; mt++) {
      const int row = m0 + wm*32 + mt*16 + g;
      *(float2*)&C[(size_t)row     * E_DIM + col] =
          make_float2(c[mt][nt][0] + bx, c[mt][nt][1] + by);
      *(float2*)&C[(size_t)(row+8) * E_DIM + col] =
          make_float2(c[mt][nt][2] + bx, c[mt][nt][3] + by);
    }
  }
}

// ===========================================================================
// Fused attention: threefry replaced by g_rng loads + exact scaled compare.
// ===========================================================================
#define QH0 0
#define QST 36
#define KH0 (3*128*36)
#define KST 36
#define VH0 (KH0 + 3*32*36)
#define VST 20
#define PP0 (VH0 + 2*64*20)
#define PST 20
#define ATTN_SMEM ((PP0 + 128*20) * 4)   // 89600 bytes

__global__ void __launch_bounds__(256, 2)
attn_kernel() {
  extern __shared__ uint32_t sm[];
  const int tid  = threadIdx.x;
  const int lane = tid & 31;
  const int warp = tid >> 5;
  const int g    = lane >> 2;
  const int tg   = lane & 3;
  const int bh   = blockIdx.y;
  const int b    = bh >> 4;
  const int h    = bh & 15;
  const int q0   = blockIdx.x << 7;

  const int wq = warp & 3;
  const int wk = warp >> 2;
  const int wm2 = warp & 3;
  const int wn2 = warp >> 2;

  // Prologue: copy packed Q
  {
    const uint32_t* src = g_Qp + ((size_t)bh * S_DIM + q0) * 32;
#pragma unroll
    for (int cc = 0; cc < 3; cc++) {
#pragma unroll
      for (int i = 0; i < 4; i++) {
        const int idx = tid + i*256;
        const int row = idx >> 3;
        const int p4  = idx & 7;
        uint4 v = *(const uint4*)(src + (size_t)cc*QP_COMP + (size_t)row*32 + p4*4);
        *(uint4*)&sm[QH0 + cc*(128*QST) + row*QST + p4*4] = v;
      }
    }
  }

  const float* Vg = g_V + (size_t)bh * S_DIM * 64;
  const uint32_t* Ksrc = g_Kp + (size_t)bh * S_DIM * 32;

  float co[2][4][4];
#pragma unroll
  for (int mt = 0; mt < 2; mt++)
#pragma unroll
    for (int nt = 0; nt < 4; nt++)
#pragma unroll
      for (int r = 0; r < 4; r++) co[mt][nt][r] = 0.0f;

  const uint32_t cbase = ((uint32_t)bh << 11) + (uint32_t)q0;

  for (int it = 0; it < 64; it++) {
    __syncthreads();

    {
      const int row = tid >> 3;
      const int p4  = tid & 7;
      const uint32_t* s0 = Ksrc + (size_t)(it*32 + row)*32 + p4*4;
#pragma unroll
      for (int cc = 0; cc < 3; cc++) {
        uint4 v = *(const uint4*)(s0 + (size_t)cc*QP_COMP);
        *(uint4*)&sm[KH0 + cc*(32*KST) + row*KST + p4*4] = v;
      }
    }
    {
      const int kp = tid & 15;
      const int d0 = (tid >> 4) * 4;
      const float* v0 = &Vg[(size_t)(it*32 + 2*kp)*64 + d0];
      float4 a = *(const float4*)v0;
      float4 bvv = *(const float4*)(v0 + 64);
      float va[4] = {a.x, a.y, a.z, a.w};
      float vb[4] = {bvv.x, bvv.y, bvv.z, bvv.w};
#pragma unroll
      for (int e = 0; e < 4; e++) {
        uint32_t hp = pack_bf16(va[e], vb[e]);
        uint32_t lp = pack_bf16(va[e] - lo_f(hp), vb[e] - hi_f(hp));
        sm[VH0 + (d0+e)*VST + kp]          = hp;
        sm[VH0 + 64*VST + (d0+e)*VST + kp] = lp;
      }
    }
    __syncthreads();

    float c[2][2][4];
#pragma unroll
    for (int mt = 0; mt < 2; mt++)
#pragma unroll
      for (int nt = 0; nt < 2; nt++)
#pragma unroll
        for (int r = 0; r < 4; r++) c[mt][nt][r] = 0.0f;

#pragma unroll
    for (int c4 = 0; c4 < 4; c4++) {
      uint32_t Ah[2][4], Am[2][4], Al[2][4];
#pragma unroll
      for (int mt = 0; mt < 2; mt++) {
        const int row = wq*32 + mt*16 + g;
        const int b0 = row*QST + c4*8;
        const int b8 = (row+8)*QST + c4*8;
        Ah[mt][0] = sm[QH0 + b0 + tg];
        Ah[mt][1] = sm[QH0 + b8 + tg];
        Ah[mt][2] = sm[QH0 + b0 + tg + 4];
        Ah[mt][3] = sm[QH0 + b8 + tg + 4];
        Am[mt][0] = sm[QH0 + 128*QST + b0 + tg];
        Am[mt][1] = sm[QH0 + 128*QST + b8 + tg];
        Am[mt][2] = sm[QH0 + 128*QST + b0 + tg + 4];
        Am[mt][3] = sm[QH0 + 128*QST + b8 + tg + 4];
        Al[mt][0] = sm[QH0 + 256*QST + b0 + tg];
        Al[mt][1] = sm[QH0 + 256*QST + b8 + tg];
        Al[mt][2] = sm[QH0 + 256*QST + b0 + tg + 4];
        Al[mt][3] = sm[QH0 + 256*QST + b8 + tg + 4];
      }
#pragma unroll
      for (int nt = 0; nt < 2; nt++) {
        const int col = wk*16 + nt*8 + g;
        const int kb  = col*KST + c4*8;
        uint32_t Bh0 = sm[KH0 + kb + tg],          Bh1 = sm[KH0 + kb + tg + 4];
        uint32_t Bm0 = sm[KH0 + 32*KST + kb + tg], Bm1 = sm[KH0 + 32*KST + kb + tg + 4];
        uint32_t Bl0 = sm[KH0 + 64*KST + kb + tg], Bl1 = sm[KH0 + 64*KST + kb + tg + 4];
#pragma unroll
        for (int mt = 0; mt < 2; mt++) {
          mma_bf16(c[mt][nt], Ah[mt], Bh0, Bh1);
          mma_bf16(c[mt][nt], Ah[mt], Bm0, Bm1);
          mma_bf16(c[mt][nt], Am[mt], Bh0, Bh1);
          mma_bf16(c[mt][nt], Ah[mt], Bl0, Bl1);
          mma_bf16(c[mt][nt], Am[mt], Bm0, Bm1);
          mma_bf16(c[mt][nt], Al[mt], Bh0, Bh1);
        }
      }
    }

    // --- sigmoid + precomputed-uniform compare (bit-identical sampling) ---
    const uint32_t ktk = (uint32_t)(it*32);
#pragma unroll
    for (int mt = 0; mt < 2; mt++) {
      const int qA = wq*32 + mt*16 + g;
      const uint32_t row0 = (cbase + (uint32_t)qA) << 11;
      const uint32_t row8 = (cbase + (uint32_t)(qA+8)) << 11;
#pragma unroll
      for (int nt = 0; nt < 2; nt++) {
        const uint32_t kl = ktk + (uint32_t)(wk*16 + nt*8 + 2*tg);
        float p0 = 1.0f / (1.0f + expf(-c[mt][nt][0] * 0.125f));
        float p1 = 1.0f / (1.0f + expf(-c[mt][nt][1] * 0.125f));
        float p2 = 1.0f / (1.0f + expf(-c[mt][nt][2] * 0.125f));
        float p3 = 1.0f / (1.0f + expf(-c[mt][nt][3] * 0.125f));
        float2 ua = *(const float2*)&g_rng[(size_t)row0 + kl];
        float2 ub = *(const float2*)&g_rng[(size_t)row8 + kl];
        // u < p  <=>  (float)(bits>>9) < p * 2^23   (both sides exact)
        const int kp = wk*8 + nt*4 + tg;
        sm[PP0 + qA*PST + kp]     = pack_bf16(ua.x < p0*8388608.0f ? 1.0f : 0.0f,
                                              ua.y < p1*8388608.0f ? 1.0f : 0.0f);
        sm[PP0 + (qA+8)*PST + kp] = pack_bf16(ub.x < p2*8388608.0f ? 1.0f : 0.0f,
                                              ub.y < p3*8388608.0f ? 1.0f : 0.0f);
      }
    }
    __syncthreads();

#pragma unroll
    for (int c4 = 0; c4 < 2; c4++) {
      uint32_t a[2][4];
#pragma unroll
      for (int mt = 0; mt < 2; mt++) {
        const int row = wm2*32 + mt*16 + g;
        a[mt][0] = sm[PP0 + row    *PST + c4*8 + tg];
        a[mt][1] = sm[PP0 + (row+8)*PST + c4*8 + tg];
        a[mt][2] = sm[PP0 + row    *PST + c4*8 + tg + 4];
        a[mt][3] = sm[PP0 + (row+8)*PST + c4*8 + tg + 4];
      }
#pragma unroll
      for (int nt = 0; nt < 4; nt++) {
        const int d = wn2*32 + nt*8 + g;
        uint32_t bh0 = sm[VH0 + d*VST + c4*8 + tg];
        uint32_t bh1 = sm[VH0 + d*VST + c4*8 + tg + 4];
        uint32_t bl0 = sm[VH0 + 64*VST + d*VST + c4*8 + tg];
        uint32_t bl1 = sm[VH0 + 64*VST + d*VST + c4*8 + tg + 4];
#pragma unroll
        for (int mt = 0; mt < 2; mt++) {
          mma_bf16(co[mt][nt], a[mt], bh0, bh1);
          mma_bf16(co[mt][nt], a[mt], bl0, bl1);
        }
      }
    }
  }

  // Epilogue: pre-split AV (h/m)
#pragma unroll
  for (int mt = 0; mt < 2; mt++) {
    const int q = q0 + wm2*32 + mt*16 + g;
    const int row = b*S_DIM + q;
#pragma unroll
    for (int nt = 0; nt < 4; nt++) {
      const int d = wn2*32 + nt*8 + tg*2;
      const int kpair = h*32 + (d >> 1);
      uint32_t hh, mm, ll;
      split3(co[mt][nt][0], co[mt][nt][1], hh, mm, ll);
      g_avp[(size_t)kpair*XROWS + row]       = hh;
      g_avp[AVC + (size_t)kpair*XROWS + row] = mm;
      split3(co[mt][nt][2], co[mt][nt][3], hh, mm, ll);
      g_avp[(size_t)kpair*XROWS + row + 8]       = hh;
      g_avp[AVC + (size_t)kpair*XROWS + row + 8] = mm;
    }
  }
}

// ===========================================================================
extern "C" void kernel_launch(void* const* d_in, const int* in_sizes, int n_in,
                              void* d_out, int out_size) {
  const float *x = nullptr, *qkv_w = nullptr, *qkv_b = nullptr;
  const float *out_w = nullptr, *out_b = nullptr;
  for (int i = 0; i < n_in; i++) {
    int sz = in_sizes[i];
    if (sz == B_DIM*S_DIM*E_DIM) { if (!x) x = (const float*)d_in[i]; }
    else if (sz == 3*E_DIM*E_DIM) qkv_w = (const float*)d_in[i];
    else if (sz == 3*E_DIM)       qkv_b = (const float*)d_in[i];
    else if (sz == E_DIM*E_DIM)   out_w = (const float*)d_in[i];
    else if (sz == E_DIM)         out_b = (const float*)d_in[i];
  }
  float* out = (float*)d_out;

  uint32_t *xp, *qwp, *owp, *avp;
  cudaGetSymbolAddress((void**)&xp,  g_xp);
  cudaGetSymbolAddress((void**)&qwp, g_qwp);
  cudaGetSymbolAddress((void**)&owp, g_owp);
  cudaGetSymbolAddress((void**)&avp, g_avp);

  // 0) pre-split static operands
  presplit<3><<<dim3(XROWS/256, KPAIRS), 256>>>(x, xp, XROWS);
  presplit<3><<<dim3(3*E_DIM/256, KPAIRS), 256>>>(qkv_w, qwp, 3*E_DIM);
  presplit<2><<<dim3(E_DIM/256, KPAIRS), 256>>>(out_w, owp, E_DIM);

  // 1) QKV from pre-split operands (+ fused RNG production)
  qkv_tc<1><<<dim3(32, 32), 256>>>(xp, qwp, qkv_b, 0);
  qkv_tc<0><<<dim3(16, 32), 256>>>(xp, qwp, qkv_b, 2048);

  // 2) fused attention (reads precomputed RNG)
  cudaFuncSetAttribute(attn_kernel, cudaFuncAttributeMaxDynamicSharedMemorySize,
                       ATTN_SMEM);
  attn_kernel<<<dim3(S_DIM/128, B_DIM*H_DIM), 256, ATTN_SMEM>>>();

  // 3) out = AV @ out_w^T + out_b
  bf16_proj<<<dim3(E_DIM/128, (B_DIM*S_DIM)/128), 256>>>(avp, owp, out_b, out);
}

// round 14
// speedup vs baseline: 1.1560x; 1.1560x over previous
#include <cuda_runtime.h>
#include <cstdint>
#include <math.h>

#define B_DIM 2
#define H_DIM 16
#define S_DIM 2048
#define E_DIM 1024
#define XROWS 4096            // B*S
#define KPAIRS 512            // 1024/2

// ---- device scratch (allocation-free rule) ----
__device__ float g_V [B_DIM*H_DIM*S_DIM*64];          // [bh][s][d] fp32
#define QP_COMP (B_DIM*H_DIM*S_DIM*32)
__device__ uint32_t g_Qp[3*QP_COMP];                  // packed Q h/m/l
__device__ uint32_t g_Kp[3*QP_COMP];
#define XC  (KPAIRS*XROWS)
__device__ uint32_t g_xp [3*XC];                      // x split h/m/l
#define WQC (KPAIRS*3*E_DIM)
__device__ uint32_t g_qwp[3*WQC];                     // qkv_w h/m/l
#define OWC (KPAIRS*E_DIM)
__device__ uint32_t g_owp[2*OWC];                     // out_w h/m
#define AVC (KPAIRS*XROWS)
__device__ uint32_t g_avp[2*AVC];                     // AV h/m (written by attn)

// ===========================================================================
// bf16 helpers
// ===========================================================================
__device__ __forceinline__ uint32_t pack_bf16(float lo, float hi) {
  uint32_t r;
  asm("cvt.rn.satfinite.bf16x2.f32 %0, %1, %2;" : "=r"(r) : "f"(hi), "f"(lo));
  return r;
}
__device__ __forceinline__ float lo_f(uint32_t u) { return __uint_as_float(u << 16); }
__device__ __forceinline__ float hi_f(uint32_t u) { return __uint_as_float(u & 0xFFFF0000u); }
__device__ __forceinline__ void split3(float fe, float fo,
                                       uint32_t& h, uint32_t& m, uint32_t& l) {
  h = pack_bf16(fe, fo);
  float re = fe - lo_f(h);
  float ro = fo - hi_f(h);
  m = pack_bf16(re, ro);
  l = pack_bf16(re - lo_f(m), ro - hi_f(m));
}
__device__ __forceinline__ void mma_bf16(float* c, const uint32_t* a,
                                         uint32_t b0, uint32_t b1) {
  asm volatile(
      "mma.sync.aligned.m16n8k16.row.col.f32.bf16.bf16.f32 "
      "{%0,%1,%2,%3},{%4,%5,%6,%7},{%8,%9},{%0,%1,%2,%3};"
      : "+f"(c[0]), "+f"(c[1]), "+f"(c[2]), "+f"(c[3])
      : "r"(a[0]), "r"(a[1]), "r"(a[2]), "r"(a[3]), "r"(b0), "r"(b1));
}

// ===========================================================================
// JAX partitionable-threefry, key (0,42)
// ===========================================================================
__device__ __forceinline__ uint32_t jax_bits_k42(uint32_t idx) {
  const uint32_t ks0 = 0u;
  const uint32_t ks1 = 42u;
  const uint32_t ks2 = 42u ^ 0x1BD11BDAu;
  uint32_t x0 = ks0;
  uint32_t x1 = idx + ks1;
#define TF_ROUND(r) { x0 += x1; x1 = __funnelshift_l(x1, x1, (r)); x1 ^= x0; }
  TF_ROUND(13) TF_ROUND(15) TF_ROUND(26) TF_ROUND(6)
  x0 += ks1; x1 += ks2 + 1u;
  TF_ROUND(17) TF_ROUND(29) TF_ROUND(16) TF_ROUND(24)
  x0 += ks2; x1 += ks0 + 2u;
  TF_ROUND(13) TF_ROUND(15) TF_ROUND(26) TF_ROUND(6)
  x0 += ks0; x1 += ks1 + 3u;
  TF_ROUND(17) TF_ROUND(29) TF_ROUND(16) TF_ROUND(24)
  x0 += ks1; x1 += ks2 + 4u;
  TF_ROUND(13) TF_ROUND(15) TF_ROUND(26) TF_ROUND(6)
  x0 += ks2; x1 += ks0 + 5u;
#undef TF_ROUND
  return x0 ^ x1;
}

// ===========================================================================
// presplit: src [rows][1024] fp32 -> dst [NC][kpair][rows] packed bf16x2
// ===========================================================================
template<int NC>
__global__ void presplit(const float* __restrict__ src,
                         uint32_t* __restrict__ dst, int nrows) {
  const int row = blockIdx.x*256 + threadIdx.x;
  const int kp  = blockIdx.y;
  float2 v = *(const float2*)(src + (size_t)row*1024 + 2*kp);
  uint32_t h, m, l;
  split3(v.x, v.y, h, m, l);
  const size_t C = (size_t)KPAIRS * nrows;
  const size_t base = (size_t)kp*nrows + row;
  dst[base] = h;
  dst[base + C] = m;
  if (NC == 3) dst[base + 2*C] = l;
}

// ===========================================================================
// qkv GEMM from pre-split operands (r12 version — NO fused RNG).
// ===========================================================================
template<int SIX>
__global__ void __launch_bounds__(256, 2)
qkv_tc(const uint32_t* __restrict__ Apk, const uint32_t* __restrict__ Wpk,
       const float* __restrict__ bias, int ncol0) {
  const int NC = SIX ? 3 : 2;
  __shared__ uint32_t As[2][3*8*136];
  __shared__ uint32_t Ws[2][3*8*72];
  const int tid  = threadIdx.x;
  const int lane = tid & 31;
  const int warp = tid >> 5;
  const int g    = lane >> 2;
  const int tg   = lane & 3;
  const int wm   = warp & 3;
  const int wn   = warp >> 2;
  const int m0   = blockIdx.y << 7;
  const int n0   = blockIdx.x << 6;

  const int akp = tid >> 5;
  const int ar4 = lane * 4;
  const int wkp = (tid >> 4) & 7;
  const int wc4 = (tid & 15) * 4;
  const bool wact = tid < 128;

  float acc[2][4][4], c[2][4][4];
#pragma unroll
  for (int mt = 0; mt < 2; mt++)
#pragma unroll
    for (int nt = 0; nt < 4; nt++)
#pragma unroll
      for (int r = 0; r < 4; r++) { acc[mt][nt][r] = 0.0f; c[mt][nt][r] = 0.0f; }

#pragma unroll
  for (int cc = 0; cc < NC; cc++) {
    uint4 a = *(const uint4*)(Apk + (size_t)cc*XC + (size_t)akp*XROWS + m0 + ar4);
    *(uint4*)&As[0][(cc*8 + akp)*136 + ar4] = a;
    if (wact) {
      uint4 w = *(const uint4*)(Wpk + (size_t)cc*WQC + (size_t)wkp*(3*E_DIM) + ncol0 + n0 + wc4);
      *(uint4*)&Ws[0][(cc*8 + wkp)*72 + wc4] = w;
    }
  }
  __syncthreads();

  uint4 av[3], wv[3];
  for (int it = 0; it < 64; it++) {
    const int buf = it & 1;
    if (it + 1 < 64) {
#pragma unroll
      for (int cc = 0; cc < NC; cc++) {
        av[cc] = *(const uint4*)(Apk + (size_t)cc*XC +
                                 (size_t)((it+1)*8 + akp)*XROWS + m0 + ar4);
        if (wact)
          wv[cc] = *(const uint4*)(Wpk + (size_t)cc*WQC +
                                   (size_t)((it+1)*8 + wkp)*(3*E_DIM) + ncol0 + n0 + wc4);
      }
    }

    uint32_t Ah[2][4], Am[2][4], Al[2][4];
#pragma unroll
    for (int mt = 0; mt < 2; mt++) {
      const int r0 = wm*32 + mt*16 + g;
#pragma unroll
      for (int p = 0; p < 4; p++) {
        const int kp = tg + ((p & 2) ? 4 : 0);
        const int rr = r0 + ((p & 1) ? 8 : 0);
        Ah[mt][p] = As[buf][(0*8 + kp)*136 + rr];
        Am[mt][p] = As[buf][(1*8 + kp)*136 + rr];
        if (SIX) Al[mt][p] = As[buf][(2*8 + kp)*136 + rr];
      }
    }

#pragma unroll
    for (int nt = 0; nt < 4; nt++) {
      const int n = wn*32 + nt*8 + g;
      uint32_t Bh0 = Ws[buf][(0*8 + tg  )*72 + n];
      uint32_t Bh1 = Ws[buf][(0*8 + tg+4)*72 + n];
      uint32_t Bm0 = Ws[buf][(1*8 + tg  )*72 + n];
      uint32_t Bm1 = Ws[buf][(1*8 + tg+4)*72 + n];
      uint32_t Bl0 = 0, Bl1 = 0;
      if (SIX) { Bl0 = Ws[buf][(2*8 + tg)*72 + n]; Bl1 = Ws[buf][(2*8 + tg+4)*72 + n]; }
#pragma unroll
      for (int mt = 0; mt < 2; mt++) {
        mma_bf16(c[mt][nt], Ah[mt], Bh0, Bh1);
        mma_bf16(c[mt][nt], Ah[mt], Bm0, Bm1);
        mma_bf16(c[mt][nt], Am[mt], Bh0, Bh1);
        if (SIX) {
          mma_bf16(c[mt][nt], Ah[mt], Bl0, Bl1);
          mma_bf16(c[mt][nt], Am[mt], Bm0, Bm1);
          mma_bf16(c[mt][nt], Al[mt], Bh0, Bh1);
        }
      }
    }

    if (it + 1 < 64) {
      const int nb = buf ^ 1;
#pragma unroll
      for (int cc = 0; cc < NC; cc++) {
        *(uint4*)&As[nb][(cc*8 + akp)*136 + ar4] = av[cc];
        if (wact) *(uint4*)&Ws[nb][(cc*8 + wkp)*72 + wc4] = wv[cc];
      }
      __syncthreads();
    }

    if ((it & 3) == 3) {
#pragma unroll
      for (int mt = 0; mt < 2; mt++)
#pragma unroll
        for (int nt = 0; nt < 4; nt++)
#pragma unroll
          for (int r = 0; r < 4; r++) {
            acc[mt][nt][r] += c[mt][nt][r];
            c[mt][nt][r] = 0.0f;
          }
    }
  }

#pragma unroll
  for (int nt = 0; nt < 4; nt++) {
    const int col = ncol0 + n0 + wn*32 + nt*8 + tg*2;
    const float bx = bias[col], by = bias[col+1];
    const int t  = col >> 10;
    const int hh = (col >> 6) & 15;
    const int d0 = col & 63;
#pragma unroll
    for (int mt = 0; mt < 2; mt++) {
      const int row = m0 + wm*32 + mt*16 + g;
      const int bb = row >> 11;
      const int s  = row & 2047;
      if (SIX) {
        uint32_t* dst = (t == 0) ? g_Qp : g_Kp;
        const size_t base = ((size_t)(bb*H_DIM + hh)*S_DIM + s)*32 + (d0 >> 1);
#pragma unroll
        for (int rr = 0; rr < 2; rr++) {
          uint32_t h, m, l;
          split3(acc[mt][nt][rr*2] + bx, acc[mt][nt][rr*2+1] + by, h, m, l);
          size_t idx = base + (size_t)rr*8*32;
          dst[idx]             = h;
          dst[idx + QP_COMP]   = m;
          dst[idx + 2*QP_COMP] = l;
        }
      } else {
        size_t base = ((size_t)(bb*H_DIM + hh)*S_DIM + s)*64 + d0;
        *(float2*)&g_V[base] =
            make_float2(acc[mt][nt][0] + bx, acc[mt][nt][1] + by);
        *(float2*)&g_V[base + 8*64] =
            make_float2(acc[mt][nt][2] + bx, acc[mt][nt][3] + by);
      }
    }
  }
}

// ===========================================================================
// proj GEMM (unchanged)
// ===========================================================================
__global__ void __launch_bounds__(256, 2)
bf16_proj(const uint32_t* __restrict__ Apk, const uint32_t* __restrict__ Wpk,
          const float* __restrict__ bias, float* __restrict__ C) {
  __shared__ uint32_t As[2*8*136];
  __shared__ uint32_t Ws[2*8*136];
  const int tid  = threadIdx.x;
  const int lane = tid & 31;
  const int warp = tid >> 5;
  const int g    = lane >> 2;
  const int tg   = lane & 3;
  const int wm   = warp & 3;
  const int wn   = warp >> 2;
  const int m0   = blockIdx.y << 7;
  const int n0   = blockIdx.x << 7;

  const int kp = tid >> 5;
  const int r4 = lane * 4;

  float c[2][8][4];
#pragma unroll
  for (int mt = 0; mt < 2; mt++)
#pragma unroll
    for (int nt = 0; nt < 8; nt++)
#pragma unroll
      for (int r = 0; r < 4; r++) c[mt][nt][r] = 0.0f;

  uint4 av[2], wv[2];
#pragma unroll
  for (int cc = 0; cc < 2; cc++) {
    av[cc] = *(const uint4*)(Apk + (size_t)cc*AVC + (size_t)kp*XROWS + m0 + r4);
    wv[cc] = *(const uint4*)(Wpk + (size_t)cc*OWC + (size_t)kp*E_DIM + n0 + r4);
  }

  for (int it = 0; it < 64; it++) {
#pragma unroll
    for (int cc = 0; cc < 2; cc++) {
      *(uint4*)&As[(cc*8 + kp)*136 + r4] = av[cc];
      *(uint4*)&Ws[(cc*8 + kp)*136 + r4] = wv[cc];
    }
    __syncthreads();
    if (it + 1 < 64) {
#pragma unroll
      for (int cc = 0; cc < 2; cc++) {
        av[cc] = *(const uint4*)(Apk + (size_t)cc*AVC +
                                 (size_t)((it+1)*8 + kp)*XROWS + m0 + r4);
        wv[cc] = *(const uint4*)(Wpk + (size_t)cc*OWC +
                                 (size_t)((it+1)*8 + kp)*E_DIM + n0 + r4);
      }
    }

    uint32_t Ah[2][4], Am[2][4];
#pragma unroll
    for (int mt = 0; mt < 2; mt++) {
      const int r0 = wm*32 + mt*16 + g;
#pragma unroll
      for (int p = 0; p < 4; p++) {
        const int kq = tg + ((p & 2) ? 4 : 0);
        const int rr = r0 + ((p & 1) ? 8 : 0);
        Ah[mt][p] = As[(0*8 + kq)*136 + rr];
        Am[mt][p] = As[(1*8 + kq)*136 + rr];
      }
    }

#pragma unroll
    for (int nt = 0; nt < 8; nt++) {
      const int n = wn*64 + nt*8 + g;
      uint32_t Bh0 = Ws[(0*8 + tg  )*136 + n];
      uint32_t Bh1 = Ws[(0*8 + tg+4)*136 + n];
      uint32_t Bm0 = Ws[(1*8 + tg  )*136 + n];
      uint32_t Bm1 = Ws[(1*8 + tg+4)*136 + n];
#pragma unroll
      for (int mt = 0; mt < 2; mt++) {
        mma_bf16(c[mt][nt], Ah[mt], Bh0, Bh1);
        mma_bf16(c[mt][nt], Ah[mt], Bm0, Bm1);
        mma_bf16(c[mt][nt], Am[mt], Bh0, Bh1);
      }
    }
    __syncthreads();
  }

#pragma unroll
  for (int nt = 0; nt < 8; nt++) {
    const int col = n0 + wn*64 + nt*8 + tg*2;
    const float bx = bias[col], by = bias[col+1];
#pragma unroll
    for (int mt = 0; mt < 2; mt++) {
      const int row = m0 + wm*32 + mt*16 + g;
      *(float2*)&C[(size_t)row     * E_DIM + col] =
          make_float2(c[mt][nt][0] + bx, c[mt][nt][1] + by);
      *(float2*)&C[(size_t)(row+8) * E_DIM + col] =
          make_float2(c[mt][nt][2] + bx, c[mt][nt][3] + by);
    }
  }
}

// ===========================================================================
// Fused attention v3: 2 phases/iter, double-buffered K/V, single Pp.
//   phase1: QK (tensor) + threefry/sigmoid (ALU) -> Pp ; sync
//   phase2: stage K/V(it+1) into alt buffer (LSU) || PV (tensor) ; sync
// smem u32: Q 3x128x36 | K 2bufs x 3x32x36 | V 2bufs x 2x64x20 | Pp 128x20
// = 113664 bytes -> still 2 CTAs/SM.
// ===========================================================================
#define QH0 0
#define QST 36
#define KH0 (3*128*36)              // 13824
#define KST 36
#define KBUF (3*32*36)              // 3456
#define VH0 (KH0 + 2*KBUF)          // 20736
#define VST 20
#define VBUF (2*64*20)              // 2560
#define PP0 (VH0 + 2*VBUF)          // 25856
#define PST 20
#define ATTN_SMEM ((PP0 + 128*20) * 4)   // 113664 bytes

__global__ void __launch_bounds__(256, 2)
attn_kernel() {
  extern __shared__ uint32_t sm[];
  const int tid  = threadIdx.x;
  const int lane = tid & 31;
  const int warp = tid >> 5;
  const int g    = lane >> 2;
  const int tg   = lane & 3;
  const int bh   = blockIdx.y;
  const int b    = bh >> 4;
  const int h    = bh & 15;
  const int q0   = blockIdx.x << 7;

  const int wq = warp & 3;
  const int wk = warp >> 2;
  const int wm2 = warp & 3;
  const int wn2 = warp >> 2;

  const float* Vg = g_V + (size_t)bh * S_DIM * 64;
  const uint32_t* Ksrc = g_Kp + (size_t)bh * S_DIM * 32;

  // staging maps (per-thread constants)
  const int krow = tid >> 3;
  const int kp4  = tid & 7;
  const int vkp  = tid & 15;
  const int vd0  = (tid >> 4) * 4;

  // Prologue: copy packed Q + stage K/V tile 0 into buf 0
  {
    const uint32_t* src = g_Qp + ((size_t)bh * S_DIM + q0) * 32;
#pragma unroll
    for (int cc = 0; cc < 3; cc++) {
#pragma unroll
      for (int i = 0; i < 4; i++) {
        const int idx = tid + i*256;
        const int row = idx >> 3;
        const int p4  = idx & 7;
        uint4 v = *(const uint4*)(src + (size_t)cc*QP_COMP + (size_t)row*32 + p4*4);
        *(uint4*)&sm[QH0 + cc*(128*QST) + row*QST + p4*4] = v;
      }
    }
    // K tile 0
    const uint32_t* s0 = Ksrc + (size_t)krow*32 + kp4*4;
#pragma unroll
    for (int cc = 0; cc < 3; cc++) {
      uint4 v = *(const uint4*)(s0 + (size_t)cc*QP_COMP);
      *(uint4*)&sm[KH0 + cc*(32*KST) + krow*KST + kp4*4] = v;
    }
    // V tile 0
    const float* v0 = &Vg[(size_t)(2*vkp)*64 + vd0];
    float4 a = *(const float4*)v0;
    float4 bvv = *(const float4*)(v0 + 64);
    float va[4] = {a.x, a.y, a.z, a.w};
    float vb[4] = {bvv.x, bvv.y, bvv.z, bvv.w};
#pragma unroll
    for (int e = 0; e < 4; e++) {
      uint32_t hp = pack_bf16(va[e], vb[e]);
      uint32_t lp = pack_bf16(va[e] - lo_f(hp), vb[e] - hi_f(hp));
      sm[VH0 + (vd0+e)*VST + vkp]          = hp;
      sm[VH0 + 64*VST + (vd0+e)*VST + vkp] = lp;
    }
  }
  __syncthreads();

  float co[2][4][4];
#pragma unroll
  for (int mt = 0; mt < 2; mt++)
#pragma unroll
    for (int nt = 0; nt < 4; nt++)
#pragma unroll
      for (int r = 0; r < 4; r++) co[mt][nt][r] = 0.0f;

  const uint32_t cbase = ((uint32_t)bh << 11) + (uint32_t)q0;

  for (int it = 0; it < 64; it++) {
    const int buf = it & 1;
    const int kbase = KH0 + buf*KBUF;
    const int vbase = VH0 + buf*VBUF;

    // ---- phase 1: QK (reads K[buf]) + threefry -> Pp ----
    float c[2][2][4];
#pragma unroll
    for (int mt = 0; mt < 2; mt++)
#pragma unroll
      for (int nt = 0; nt < 2; nt++)
#pragma unroll
        for (int r = 0; r < 4; r++) c[mt][nt][r] = 0.0f;

#pragma unroll
    for (int c4 = 0; c4 < 4; c4++) {
      uint32_t Ah[2][4], Am[2][4], Al[2][4];
#pragma unroll
      for (int mt = 0; mt < 2; mt++) {
        const int row = wq*32 + mt*16 + g;
        const int b0 = row*QST + c4*8;
        const int b8 = (row+8)*QST + c4*8;
        Ah[mt][0] = sm[QH0 + b0 + tg];
        Ah[mt][1] = sm[QH0 + b8 + tg];
        Ah[mt][2] = sm[QH0 + b0 + tg + 4];
        Ah[mt][3] = sm[QH0 + b8 + tg + 4];
        Am[mt][0] = sm[QH0 + 128*QST + b0 + tg];
        Am[mt][1] = sm[QH0 + 128*QST + b8 + tg];
        Am[mt][2] = sm[QH0 + 128*QST + b0 + tg + 4];
        Am[mt][3] = sm[QH0 + 128*QST + b8 + tg + 4];
        Al[mt][0] = sm[QH0 + 256*QST + b0 + tg];
        Al[mt][1] = sm[QH0 + 256*QST + b8 + tg];
        Al[mt][2] = sm[QH0 + 256*QST + b0 + tg + 4];
        Al[mt][3] = sm[QH0 + 256*QST + b8 + tg + 4];
      }
#pragma unroll
      for (int nt = 0; nt < 2; nt++) {
        const int col = wk*16 + nt*8 + g;
        const int kb  = kbase + col*KST + c4*8;
        uint32_t Bh0 = sm[kb + tg],          Bh1 = sm[kb + tg + 4];
        uint32_t Bm0 = sm[32*KST + kb + tg], Bm1 = sm[32*KST + kb + tg + 4];
        uint32_t Bl0 = sm[64*KST + kb + tg], Bl1 = sm[64*KST + kb + tg + 4];
#pragma unroll
        for (int mt = 0; mt < 2; mt++) {
          mma_bf16(c[mt][nt], Ah[mt], Bh0, Bh1);
          mma_bf16(c[mt][nt], Ah[mt], Bm0, Bm1);
          mma_bf16(c[mt][nt], Am[mt], Bh0, Bh1);
          mma_bf16(c[mt][nt], Ah[mt], Bl0, Bl1);
          mma_bf16(c[mt][nt], Am[mt], Bm0, Bm1);
          mma_bf16(c[mt][nt], Al[mt], Bh0, Bh1);
        }
      }
    }

    const uint32_t ktk = (uint32_t)(it*32);
#pragma unroll
    for (int mt = 0; mt < 2; mt++) {
      const int qA = wq*32 + mt*16 + g;
      const uint32_t row0 = (cbase + (uint32_t)qA) << 11;
      const uint32_t row8 = (cbase + (uint32_t)(qA+8)) << 11;
#pragma unroll
      for (int nt = 0; nt < 2; nt++) {
        const uint32_t kl = ktk + (uint32_t)(wk*16 + nt*8 + 2*tg);
        float p0 = 1.0f / (1.0f + expf(-c[mt][nt][0] * 0.125f));
        float p1 = 1.0f / (1.0f + expf(-c[mt][nt][1] * 0.125f));
        float p2 = 1.0f / (1.0f + expf(-c[mt][nt][2] * 0.125f));
        float p3 = 1.0f / (1.0f + expf(-c[mt][nt][3] * 0.125f));
        uint32_t b0 = jax_bits_k42(row0 + kl);
        uint32_t b1 = jax_bits_k42(row0 + kl + 1u);
        uint32_t b2 = jax_bits_k42(row8 + kl);
        uint32_t b3 = jax_bits_k42(row8 + kl + 1u);
        float u0 = __uint_as_float((b0 >> 9) | 0x3f800000u) - 1.0f;
        float u1 = __uint_as_float((b1 >> 9) | 0x3f800000u) - 1.0f;
        float u2 = __uint_as_float((b2 >> 9) | 0x3f800000u) - 1.0f;
        float u3 = __uint_as_float((b3 >> 9) | 0x3f800000u) - 1.0f;
        const int kp = wk*8 + nt*4 + tg;
        sm[PP0 + qA*PST + kp]     = pack_bf16(u0 < p0 ? 1.0f : 0.0f,
                                              u1 < p1 ? 1.0f : 0.0f);
        sm[PP0 + (qA+8)*PST + kp] = pack_bf16(u2 < p2 ? 1.0f : 0.0f,
                                              u3 < p3 ? 1.0f : 0.0f);
      }
    }
    __syncthreads();

    // ---- phase 2: stage next K/V (alt buffer) overlapped with PV ----
    if (it + 1 < 64) {
      const int nb = buf ^ 1;
      const uint32_t* s0 = Ksrc + (size_t)((it+1)*32 + krow)*32 + kp4*4;
#pragma unroll
      for (int cc = 0; cc < 3; cc++) {
        uint4 v = *(const uint4*)(s0 + (size_t)cc*QP_COMP);
        *(uint4*)&sm[KH0 + nb*KBUF + cc*(32*KST) + krow*KST + kp4*4] = v;
      }
      const float* v0 = &Vg[(size_t)((it+1)*32 + 2*vkp)*64 + vd0];
      float4 a = *(const float4*)v0;
      float4 bvv = *(const float4*)(v0 + 64);
      float va[4] = {a.x, a.y, a.z, a.w};
      float vb[4] = {bvv.x, bvv.y, bvv.z, bvv.w};
#pragma unroll
      for (int e = 0; e < 4; e++) {
        uint32_t hp = pack_bf16(va[e], vb[e]);
        uint32_t lp = pack_bf16(va[e] - lo_f(hp), vb[e] - hi_f(hp));
        sm[VH0 + nb*VBUF + (vd0+e)*VST + vkp]          = hp;
        sm[VH0 + nb*VBUF + 64*VST + (vd0+e)*VST + vkp] = lp;
      }
    }

#pragma unroll
    for (int c4 = 0; c4 < 2; c4++) {
      uint32_t a[2][4];
#pragma unroll
      for (int mt = 0; mt < 2; mt++) {
        const int row = wm2*32 + mt*16 + g;
        a[mt][0] = sm[PP0 + row    *PST + c4*8 + tg];
        a[mt][1] = sm[PP0 + (row+8)*PST + c4*8 + tg];
        a[mt][2] = sm[PP0 + row    *PST + c4*8 + tg + 4];
        a[mt][3] = sm[PP0 + (row+8)*PST + c4*8 + tg + 4];
      }
#pragma unroll
      for (int nt = 0; nt < 4; nt++) {
        const int d = wn2*32 + nt*8 + g;
        uint32_t bh0 = sm[vbase + d*VST + c4*8 + tg];
        uint32_t bh1 = sm[vbase + d*VST + c4*8 + tg + 4];
        uint32_t bl0 = sm[vbase + 64*VST + d*VST + c4*8 + tg];
        uint32_t bl1 = sm[vbase + 64*VST + d*VST + c4*8 + tg + 4];
#pragma unroll
        for (int mt = 0; mt < 2; mt++) {
          mma_bf16(co[mt][nt], a[mt], bh0, bh1);
          mma_bf16(co[mt][nt], a[mt], bl0, bl1);
        }
      }
    }
    __syncthreads();
  }

  // Epilogue: pre-split AV (h/m)
#pragma unroll
  for (int mt = 0; mt < 2; mt++) {
    const int q = q0 + wm2*32 + mt*16 + g;
    const int row = b*S_DIM + q;
#pragma unroll
    for (int nt = 0; nt < 4; nt++) {
      const int d = wn2*32 + nt*8 + tg*2;
      const int kpair = h*32 + (d >> 1);
      uint32_t hh, mm, ll;
      split3(co[mt][nt][0], co[mt][nt][1], hh, mm, ll);
      g_avp[(size_t)kpair*XROWS + row]       = hh;
      g_avp[AVC + (size_t)kpair*XROWS + row] = mm;
      split3(co[mt][nt][2], co[mt][nt][3], hh, mm, ll);
      g_avp[(size_t)kpair*XROWS + row + 8]       = hh;
      g_avp[AVC + (size_t)kpair*XROWS + row + 8] = mm;
    }
  }
}

// ===========================================================================
extern "C" void kernel_launch(void* const* d_in, const int* in_sizes, int n_in,
                              void* d_out, int out_size) {
  const float *x = nullptr, *qkv_w = nullptr, *qkv_b = nullptr;
  const float *out_w = nullptr, *out_b = nullptr;
  for (int i = 0; i < n_in; i++) {
    int sz = in_sizes[i];
    if (sz == B_DIM*S_DIM*E_DIM) { if (!x) x = (const float*)d_in[i]; }
    else if (sz == 3*E_DIM*E_DIM) qkv_w = (const float*)d_in[i];
    else if (sz == 3*E_DIM)       qkv_b = (const float*)d_in[i];
    else if (sz == E_DIM*E_DIM)   out_w = (const float*)d_in[i];
    else if (sz == E_DIM)         out_b = (const float*)d_in[i];
  }
  float* out = (float*)d_out;

  uint32_t *xp, *qwp, *owp, *avp;
  cudaGetSymbolAddress((void**)&xp,  g_xp);
  cudaGetSymbolAddress((void**)&qwp, g_qwp);
  cudaGetSymbolAddress((void**)&owp, g_owp);
  cudaGetSymbolAddress((void**)&avp, g_avp);

  // 0) pre-split static operands
  presplit<3><<<dim3(XROWS/256, KPAIRS), 256>>>(x, xp, XROWS);
  presplit<3><<<dim3(3*E_DIM/256, KPAIRS), 256>>>(qkv_w, qwp, 3*E_DIM);
  presplit<2><<<dim3(E_DIM/256, KPAIRS), 256>>>(out_w, owp, E_DIM);

  // 1) QKV from pre-split operands
  qkv_tc<1><<<dim3(32, 32), 256>>>(xp, qwp, qkv_b, 0);
  qkv_tc<0><<<dim3(16, 32), 256>>>(xp, qwp, qkv_b, 2048);

  // 2) fused attention (2-phase pipelined)
  cudaFuncSetAttribute(attn_kernel, cudaFuncAttributeMaxDynamicSharedMemorySize,
                       ATTN_SMEM);
  attn_kernel<<<dim3(S_DIM/128, B_DIM*H_DIM), 256, ATTN_SMEM>>>();

  // 3) out = AV @ out_w^T + out_b
  bf16_proj<<<dim3(E_DIM/128, (B_DIM*S_DIM)/128), 256>>>(avp, owp, out_b, out);
}

// round 16
// speedup vs baseline: 1.2516x; 1.0827x over previous
#include <cuda_runtime.h>
#include <cstdint>
#include <math.h>

#define B_DIM 2
#define H_DIM 16
#define S_DIM 2048
#define E_DIM 1024
#define XROWS 4096            // B*S
#define KPAIRS 512            // 1024/2

// ---- device scratch (allocation-free rule) ----
__device__ float g_V [B_DIM*H_DIM*S_DIM*64];          // [bh][s][d] fp32
#define QP_COMP (B_DIM*H_DIM*S_DIM*32)
__device__ uint32_t g_Qp[3*QP_COMP];                  // packed Q h/m/l
__device__ uint32_t g_Kp[3*QP_COMP];
#define XC  (KPAIRS*XROWS)
__device__ uint32_t g_xp [3*XC];                      // x split h/m/l
#define WQC (KPAIRS*3*E_DIM)
__device__ uint32_t g_qwp[3*WQC];                     // qkv_w h/m/l
#define OWC (KPAIRS*E_DIM)
__device__ uint32_t g_owp[2*OWC];                     // out_w h/m
#define AVC (KPAIRS*XROWS)
__device__ uint32_t g_avp[2*AVC];                     // AV h/m (written by attn)

// ===========================================================================
// bf16 helpers
// ===========================================================================
__device__ __forceinline__ uint32_t pack_bf16(float lo, float hi) {
  uint32_t r;
  asm("cvt.rn.satfinite.bf16x2.f32 %0, %1, %2;" : "=r"(r) : "f"(hi), "f"(lo));
  return r;
}
__device__ __forceinline__ float lo_f(uint32_t u) { return __uint_as_float(u << 16); }
__device__ __forceinline__ float hi_f(uint32_t u) { return __uint_as_float(u & 0xFFFF0000u); }
__device__ __forceinline__ void split3(float fe, float fo,
                                       uint32_t& h, uint32_t& m, uint32_t& l) {
  h = pack_bf16(fe, fo);
  float re = fe - lo_f(h);
  float ro = fo - hi_f(h);
  m = pack_bf16(re, ro);
  l = pack_bf16(re - lo_f(m), ro - hi_f(m));
}
__device__ __forceinline__ void mma_bf16(float* c, const uint32_t* a,
                                         uint32_t b0, uint32_t b1) {
  asm volatile(
      "mma.sync.aligned.m16n8k16.row.col.f32.bf16.bf16.f32 "
      "{%0,%1,%2,%3},{%4,%5,%6,%7},{%8,%9},{%0,%1,%2,%3};"
      : "+f"(c[0]), "+f"(c[1]), "+f"(c[2]), "+f"(c[3])
      : "r"(a[0]), "r"(a[1]), "r"(a[2]), "r"(a[3]), "r"(b0), "r"(b1));
}

// ===========================================================================
// JAX partitionable-threefry, key (0,42)
// ===========================================================================
__device__ __forceinline__ uint32_t jax_bits_k42(uint32_t idx) {
  const uint32_t ks0 = 0u;
  const uint32_t ks1 = 42u;
  const uint32_t ks2 = 42u ^ 0x1BD11BDAu;
  uint32_t x0 = ks0;
  uint32_t x1 = idx + ks1;
#define TF_ROUND(r) { x0 += x1; x1 = __funnelshift_l(x1, x1, (r)); x1 ^= x0; }
  TF_ROUND(13) TF_ROUND(15) TF_ROUND(26) TF_ROUND(6)
  x0 += ks1; x1 += ks2 + 1u;
  TF_ROUND(17) TF_ROUND(29) TF_ROUND(16) TF_ROUND(24)
  x0 += ks2; x1 += ks0 + 2u;
  TF_ROUND(13) TF_ROUND(15) TF_ROUND(26) TF_ROUND(6)
  x0 += ks0; x1 += ks1 + 3u;
  TF_ROUND(17) TF_ROUND(29) TF_ROUND(16) TF_ROUND(24)
  x0 += ks1; x1 += ks2 + 4u;
  TF_ROUND(13) TF_ROUND(15) TF_ROUND(26) TF_ROUND(6)
  x0 += ks2; x1 += ks0 + 5u;
#undef TF_ROUND
  return x0 ^ x1;
}

// ===========================================================================
// presplit (unchanged r12)
// ===========================================================================
template<int NC>
__global__ void presplit(const float* __restrict__ src,
                         uint32_t* __restrict__ dst, int nrows) {
  const int row = blockIdx.x*256 + threadIdx.x;
  const int kp  = blockIdx.y;
  float2 v = *(const float2*)(src + (size_t)row*1024 + 2*kp);
  uint32_t h, m, l;
  split3(v.x, v.y, h, m, l);
  const size_t C = (size_t)KPAIRS * nrows;
  const size_t base = (size_t)kp*nrows + row;
  dst[base] = h;
  dst[base + C] = m;
  if (NC == 3) dst[base + 2*C] = l;
}

// ===========================================================================
// qkv GEMM (unchanged r12)
// ===========================================================================
template<int SIX>
__global__ void __launch_bounds__(256, 2)
qkv_tc(const uint32_t* __restrict__ Apk, const uint32_t* __restrict__ Wpk,
       const float* __restrict__ bias, int ncol0) {
  const int NC = SIX ? 3 : 2;
  __shared__ uint32_t As[2][3*8*136];
  __shared__ uint32_t Ws[2][3*8*72];
  const int tid  = threadIdx.x;
  const int lane = tid & 31;
  const int warp = tid >> 5;
  const int g    = lane >> 2;
  const int tg   = lane & 3;
  const int wm   = warp & 3;
  const int wn   = warp >> 2;
  const int m0   = blockIdx.y << 7;
  const int n0   = blockIdx.x << 6;

  const int akp = tid >> 5;
  const int ar4 = lane * 4;
  const int wkp = (tid >> 4) & 7;
  const int wc4 = (tid & 15) * 4;
  const bool wact = tid < 128;

  float acc[2][4][4], c[2][4][4];
#pragma unroll
  for (int mt = 0; mt < 2; mt++)
#pragma unroll
    for (int nt = 0; nt < 4; nt++)
#pragma unroll
      for (int r = 0; r < 4; r++) { acc[mt][nt][r] = 0.0f; c[mt][nt][r] = 0.0f; }

#pragma unroll
  for (int cc = 0; cc < NC; cc++) {
    uint4 a = *(const uint4*)(Apk + (size_t)cc*XC + (size_t)akp*XROWS + m0 + ar4);
    *(uint4*)&As[0][(cc*8 + akp)*136 + ar4] = a;
    if (wact) {
      uint4 w = *(const uint4*)(Wpk + (size_t)cc*WQC + (size_t)wkp*(3*E_DIM) + ncol0 + n0 + wc4);
      *(uint4*)&Ws[0][(cc*8 + wkp)*72 + wc4] = w;
    }
  }
  __syncthreads();

  uint4 av[3], wv[3];
  for (int it = 0; it < 64; it++) {
    const int buf = it & 1;
    if (it + 1 < 64) {
#pragma unroll
      for (int cc = 0; cc < NC; cc++) {
        av[cc] = *(const uint4*)(Apk + (size_t)cc*XC +
                                 (size_t)((it+1)*8 + akp)*XROWS + m0 + ar4);
        if (wact)
          wv[cc] = *(const uint4*)(Wpk + (size_t)cc*WQC +
                                   (size_t)((it+1)*8 + wkp)*(3*E_DIM) + ncol0 + n0 + wc4);
      }
    }

    uint32_t Ah[2][4], Am[2][4], Al[2][4];
#pragma unroll
    for (int mt = 0; mt < 2; mt++) {
      const int r0 = wm*32 + mt*16 + g;
#pragma unroll
      for (int p = 0; p < 4; p++) {
        const int kp = tg + ((p & 2) ? 4 : 0);
        const int rr = r0 + ((p & 1) ? 8 : 0);
        Ah[mt][p] = As[buf][(0*8 + kp)*136 + rr];
        Am[mt][p] = As[buf][(1*8 + kp)*136 + rr];
        if (SIX) Al[mt][p] = As[buf][(2*8 + kp)*136 + rr];
      }
    }

#pragma unroll
    for (int nt = 0; nt < 4; nt++) {
      const int n = wn*32 + nt*8 + g;
      uint32_t Bh0 = Ws[buf][(0*8 + tg  )*72 + n];
      uint32_t Bh1 = Ws[buf][(0*8 + tg+4)*72 + n];
      uint32_t Bm0 = Ws[buf][(1*8 + tg  )*72 + n];
      uint32_t Bm1 = Ws[buf][(1*8 + tg+4)*72 + n];
      uint32_t Bl0 = 0, Bl1 = 0;
      if (SIX) { Bl0 = Ws[buf][(2*8 + tg)*72 + n]; Bl1 = Ws[buf][(2*8 + tg+4)*72 + n]; }
#pragma unroll
      for (int mt = 0; mt < 2; mt++) {
        mma_bf16(c[mt][nt], Ah[mt], Bh0, Bh1);
        mma_bf16(c[mt][nt], Ah[mt], Bm0, Bm1);
        mma_bf16(c[mt][nt], Am[mt], Bh0, Bh1);
        if (SIX) {
          mma_bf16(c[mt][nt], Ah[mt], Bl0, Bl1);
          mma_bf16(c[mt][nt], Am[mt], Bm0, Bm1);
          mma_bf16(c[mt][nt], Al[mt], Bh0, Bh1);
        }
      }
    }

    if (it + 1 < 64) {
      const int nb = buf ^ 1;
#pragma unroll
      for (int cc = 0; cc < NC; cc++) {
        *(uint4*)&As[nb][(cc*8 + akp)*136 + ar4] = av[cc];
        if (wact) *(uint4*)&Ws[nb][(cc*8 + wkp)*72 + wc4] = wv[cc];
      }
      __syncthreads();
    }

    if ((it & 3) == 3) {
#pragma unroll
      for (int mt = 0; mt < 2; mt++)
#pragma unroll
        for (int nt = 0; nt < 4; nt++)
#pragma unroll
          for (int r = 0; r < 4; r++) {
            acc[mt][nt][r] += c[mt][nt][r];
            c[mt][nt][r] = 0.0f;
          }
    }
  }

#pragma unroll
  for (int nt = 0; nt < 4; nt++) {
    const int col = ncol0 + n0 + wn*32 + nt*8 + tg*2;
    const float bx = bias[col], by = bias[col+1];
    const int t  = col >> 10;
    const int hh = (col >> 6) & 15;
    const int d0 = col & 63;
#pragma unroll
    for (int mt = 0; mt < 2; mt++) {
      const int row = m0 + wm*32 + mt*16 + g;
      const int bb = row >> 11;
      const int s  = row & 2047;
      if (SIX) {
        uint32_t* dst = (t == 0) ? g_Qp : g_Kp;
        const size_t base = ((size_t)(bb*H_DIM + hh)*S_DIM + s)*32 + (d0 >> 1);
#pragma unroll
        for (int rr = 0; rr < 2; rr++) {
          uint32_t h, m, l;
          split3(acc[mt][nt][rr*2] + bx, acc[mt][nt][rr*2+1] + by, h, m, l);
          size_t idx = base + (size_t)rr*8*32;
          dst[idx]             = h;
          dst[idx + QP_COMP]   = m;
          dst[idx + 2*QP_COMP] = l;
        }
      } else {
        size_t base = ((size_t)(bb*H_DIM + hh)*S_DIM + s)*64 + d0;
        *(float2*)&g_V[base] =
            make_float2(acc[mt][nt][0] + bx, acc[mt][nt][1] + by);
        *(float2*)&g_V[base + 8*64] =
            make_float2(acc[mt][nt][2] + bx, acc[mt][nt][3] + by);
      }
    }
  }
}

// ===========================================================================
// proj GEMM (unchanged r12)
// ===========================================================================
__global__ void __launch_bounds__(256, 2)
bf16_proj(const uint32_t* __restrict__ Apk, const uint32_t* __restrict__ Wpk,
          const float* __restrict__ bias, float* __restrict__ C) {
  __shared__ uint32_t As[2*8*136];
  __shared__ uint32_t Ws[2*8*136];
  const int tid  = threadIdx.x;
  const int lane = tid & 31;
  const int warp = tid >> 5;
  const int g    = lane >> 2;
  const int tg   = lane & 3;
  const int wm   = warp & 3;
  const int wn   = warp >> 2;
  const int m0   = blockIdx.y << 7;
  const int n0   = blockIdx.x << 7;

  const int kp = tid >> 5;
  const int r4 = lane * 4;

  float c[2][8][4];
#pragma unroll
  for (int mt = 0; mt < 2; mt++)
#pragma unroll
    for (int nt = 0; nt < 8; nt++)
#pragma unroll
      for (int r = 0; r < 4; r++) c[mt][nt][r] = 0.0f;

  uint4 av[2], wv[2];
#pragma unroll
  for (int cc = 0; cc < 2; cc++) {
    av[cc] = *(const uint4*)(Apk + (size_t)cc*AVC + (size_t)kp*XROWS + m0 + r4);
    wv[cc] = *(const uint4*)(Wpk + (size_t)cc*OWC + (size_t)kp*E_DIM + n0 + r4);
  }

  for (int it = 0; it < 64; it++) {
#pragma unroll
    for (int cc = 0; cc < 2; cc++) {
      *(uint4*)&As[(cc*8 + kp)*136 + r4] = av[cc];
      *(uint4*)&Ws[(cc*8 + kp)*136 + r4] = wv[cc];
    }
    __syncthreads();
    if (it + 1 < 64) {
#pragma unroll
      for (int cc = 0; cc < 2; cc++) {
        av[cc] = *(const uint4*)(Apk + (size_t)cc*AVC +
                                 (size_t)((it+1)*8 + kp)*XROWS + m0 + r4);
        wv[cc] = *(const uint4*)(Wpk + (size_t)cc*OWC +
                                 (size_t)((it+1)*8 + kp)*E_DIM + n0 + r4);
      }
    }

    uint32_t Ah[2][4], Am[2][4];
#pragma unroll
    for (int mt = 0; mt < 2; mt++) {
      const int r0 = wm*32 + mt*16 + g;
#pragma unroll
      for (int p = 0; p < 4; p++) {
        const int kq = tg + ((p & 2) ? 4 : 0);
        const int rr = r0 + ((p & 1) ? 8 : 0);
        Ah[mt][p] = As[(0*8 + kq)*136 + rr];
        Am[mt][p] = As[(1*8 + kq)*136 + rr];
      }
    }

#pragma unroll
    for (int nt = 0; nt < 8; nt++) {
      const int n = wn*64 + nt*8 + g;
      uint32_t Bh0 = Ws[(0*8 + tg  )*136 + n];
      uint32_t Bh1 = Ws[(0*8 + tg+4)*136 + n];
      uint32_t Bm0 = Ws[(1*8 + tg  )*136 + n];
      uint32_t Bm1 = Ws[(1*8 + tg+4)*136 + n];
#pragma unroll
      for (int mt = 0; mt < 2; mt++) {
        mma_bf16(c[mt][nt], Ah[mt], Bh0, Bh1);
        mma_bf16(c[mt][nt], Ah[mt], Bm0, Bm1);
        mma_bf16(c[mt][nt], Am[mt], Bh0, Bh1);
      }
    }
    __syncthreads();
  }

#pragma unroll
  for (int nt = 0; nt < 8; nt++) {
    const int col = n0 + wn*64 + nt*8 + tg*2;
    const float bx = bias[col], by = bias[col+1];
#pragma unroll
    for (int mt = 0; mt < 2; mt++) {
      const int row = m0 + wm*32 + mt*16 + g;
      *(float2*)&C[(size_t)row     * E_DIM + col] =
          make_float2(c[mt][nt][0] + bx, c[mt][nt][1] + by);
      *(float2*)&C[(size_t)(row+8) * E_DIM + col] =
          make_float2(c[mt][nt][2] + bx, c[mt][nt][3] + by);
    }
  }
}

// ===========================================================================
// Fused attention v4b: q-tile 64, 128 threads, 4 CTAs/SM.
// FIX vs r15: PV warp tile is 32q x 32d (wm2=warp&1, wn2=warp>>1, nt<4)
// so all 64 d-columns are produced. Math bit-identical to r12.
// smem u32: Q 3x64x36 | K 3x32x36 | V 2x64x20 | Pp 64x20 = 14208 (56832 B)
// ===========================================================================
#define QH0 0
#define QST 36
#define KH0 (3*64*36)               // 6912
#define KST 36
#define VH0 (KH0 + 3*32*36)         // 10368
#define VST 20
#define PP0 (VH0 + 2*64*20)         // 12928
#define PST 20
#define ATTN_SMEM ((PP0 + 64*20) * 4)   // 56832 bytes

__global__ void __launch_bounds__(128, 4)
attn_kernel() {
  extern __shared__ uint32_t sm[];
  const int tid  = threadIdx.x;
  const int lane = tid & 31;
  const int warp = tid >> 5;          // 0..3
  const int g    = lane >> 2;
  const int tg   = lane & 3;
  const int bh   = blockIdx.y;
  const int b    = bh >> 4;
  const int h    = bh & 15;
  const int q0   = blockIdx.x << 6;   // q-tile 64

  const int wq  = warp & 1;           // QK q 32-group (0..1)
  const int wk  = warp >> 1;          // QK k 16-group (0..1)
  const int wm2 = warp & 1;           // PV q 32-group (0..1)
  const int wn2 = warp >> 1;          // PV d 32-group (0..1)

  const float* Vg = g_V + (size_t)bh * S_DIM * 64;
  const uint32_t* Ksrc = g_Kp + (size_t)bh * S_DIM * 32;

  // Prologue: copy packed Q (3 comps x 64 rows x 8 uint4)
  {
    const uint32_t* src = g_Qp + ((size_t)bh * S_DIM + q0) * 32;
#pragma unroll
    for (int cc = 0; cc < 3; cc++) {
#pragma unroll
      for (int i = 0; i < 4; i++) {
        const int idx = tid + i*128;       // 512 uint4 per comp
        const int row = idx >> 3;
        const int p4  = idx & 7;
        uint4 v = *(const uint4*)(src + (size_t)cc*QP_COMP + (size_t)row*32 + p4*4);
        *(uint4*)&sm[QH0 + cc*(64*QST) + row*QST + p4*4] = v;
      }
    }
  }

  float co[2][4][4];   // PV accumulators: 2 q16 x 4 d8
#pragma unroll
  for (int mt = 0; mt < 2; mt++)
#pragma unroll
    for (int nt = 0; nt < 4; nt++)
#pragma unroll
      for (int r = 0; r < 4; r++) co[mt][nt][r] = 0.0f;

  const uint32_t cbase = ((uint32_t)bh << 11) + (uint32_t)q0;

  // staging maps
  const int vkp = tid & 15;            // V k-pair
  const int vd0 = (tid >> 4) * 8;      // V d block of 8

  for (int it = 0; it < 64; it++) {
    __syncthreads();   // prior PV reads done before K/V/Pp overwrite

    // stage K: 3 comps x 32 rows x 8 uint4 (2 uint4/thread/comp)
    {
#pragma unroll
      for (int j = 0; j < 2; j++) {
        const int idx = tid + j*128;
        const int row = idx >> 3;
        const int p4  = idx & 7;
        const uint32_t* s0 = Ksrc + (size_t)(it*32 + row)*32 + p4*4;
#pragma unroll
        for (int cc = 0; cc < 3; cc++) {
          uint4 v = *(const uint4*)(s0 + (size_t)cc*QP_COMP);
          *(uint4*)&sm[KH0 + cc*(32*KST) + row*KST + p4*4] = v;
        }
      }
    }
    // stage V: split x2; each thread: k-pair vkp, d block vd0..vd0+7
    {
      const float* v0 = &Vg[(size_t)(it*32 + 2*vkp)*64 + vd0];
      float4 a0 = *(const float4*)v0;
      float4 a1 = *(const float4*)(v0 + 4);
      float4 b0 = *(const float4*)(v0 + 64);
      float4 b1 = *(const float4*)(v0 + 68);
      float va[8] = {a0.x,a0.y,a0.z,a0.w,a1.x,a1.y,a1.z,a1.w};
      float vb[8] = {b0.x,b0.y,b0.z,b0.w,b1.x,b1.y,b1.z,b1.w};
#pragma unroll
      for (int e = 0; e < 8; e++) {
        uint32_t hp = pack_bf16(va[e], vb[e]);
        uint32_t lp = pack_bf16(va[e] - lo_f(hp), vb[e] - hi_f(hp));
        sm[VH0 + (vd0+e)*VST + vkp]          = hp;
        sm[VH0 + 64*VST + (vd0+e)*VST + vkp] = lp;
      }
    }
    __syncthreads();

    // --- QK bf16x6: warp tile 32q x 16k ---
    float c[2][2][4];
#pragma unroll
    for (int mt = 0; mt < 2; mt++)
#pragma unroll
      for (int nt = 0; nt < 2; nt++)
#pragma unroll
        for (int r = 0; r < 4; r++) c[mt][nt][r] = 0.0f;

#pragma unroll
    for (int c4 = 0; c4 < 4; c4++) {
      uint32_t Ah[2][4], Am[2][4], Al[2][4];
#pragma unroll
      for (int mt = 0; mt < 2; mt++) {
        const int row = wq*32 + mt*16 + g;
        const int b0 = row*QST + c4*8;
        const int b8 = (row+8)*QST + c4*8;
        Ah[mt][0] = sm[QH0 + b0 + tg];
        Ah[mt][1] = sm[QH0 + b8 + tg];
        Ah[mt][2] = sm[QH0 + b0 + tg + 4];
        Ah[mt][3] = sm[QH0 + b8 + tg + 4];
        Am[mt][0] = sm[QH0 + 64*QST + b0 + tg];
        Am[mt][1] = sm[QH0 + 64*QST + b8 + tg];
        Am[mt][2] = sm[QH0 + 64*QST + b0 + tg + 4];
        Am[mt][3] = sm[QH0 + 64*QST + b8 + tg + 4];
        Al[mt][0] = sm[QH0 + 128*QST + b0 + tg];
        Al[mt][1] = sm[QH0 + 128*QST + b8 + tg];
        Al[mt][2] = sm[QH0 + 128*QST + b0 + tg + 4];
        Al[mt][3] = sm[QH0 + 128*QST + b8 + tg + 4];
      }
#pragma unroll
      for (int nt = 0; nt < 2; nt++) {
        const int col = wk*16 + nt*8 + g;
        const int kb  = KH0 + col*KST + c4*8;
        uint32_t Bh0 = sm[kb + tg],          Bh1 = sm[kb + tg + 4];
        uint32_t Bm0 = sm[32*KST + kb + tg], Bm1 = sm[32*KST + kb + tg + 4];
        uint32_t Bl0 = sm[64*KST + kb + tg], Bl1 = sm[64*KST + kb + tg + 4];
#pragma unroll
        for (int mt = 0; mt < 2; mt++) {
          mma_bf16(c[mt][nt], Ah[mt], Bh0, Bh1);
          mma_bf16(c[mt][nt], Ah[mt], Bm0, Bm1);
          mma_bf16(c[mt][nt], Am[mt], Bh0, Bh1);
          mma_bf16(c[mt][nt], Ah[mt], Bl0, Bl1);
          mma_bf16(c[mt][nt], Am[mt], Bm0, Bm1);
          mma_bf16(c[mt][nt], Al[mt], Bh0, Bh1);
        }
      }
    }

    // --- sigmoid + threefry -> Pp (identical math) ---
    const uint32_t ktk = (uint32_t)(it*32);
#pragma unroll
    for (int mt = 0; mt < 2; mt++) {
      const int qA = wq*32 + mt*16 + g;
      const uint32_t row0 = (cbase + (uint32_t)qA) << 11;
      const uint32_t row8 = (cbase + (uint32_t)(qA+8)) << 11;
#pragma unroll
      for (int nt = 0; nt < 2; nt++) {
        const uint32_t kl = ktk + (uint32_t)(wk*16 + nt*8 + 2*tg);
        float p0 = 1.0f / (1.0f + expf(-c[mt][nt][0] * 0.125f));
        float p1 = 1.0f / (1.0f + expf(-c[mt][nt][1] * 0.125f));
        float p2 = 1.0f / (1.0f + expf(-c[mt][nt][2] * 0.125f));
        float p3 = 1.0f / (1.0f + expf(-c[mt][nt][3] * 0.125f));
        uint32_t b0 = jax_bits_k42(row0 + kl);
        uint32_t b1 = jax_bits_k42(row0 + kl + 1u);
        uint32_t b2 = jax_bits_k42(row8 + kl);
        uint32_t b3 = jax_bits_k42(row8 + kl + 1u);
        float u0 = __uint_as_float((b0 >> 9) | 0x3f800000u) - 1.0f;
        float u1 = __uint_as_float((b1 >> 9) | 0x3f800000u) - 1.0f;
        float u2 = __uint_as_float((b2 >> 9) | 0x3f800000u) - 1.0f;
        float u3 = __uint_as_float((b3 >> 9) | 0x3f800000u) - 1.0f;
        const int kp = wk*8 + nt*4 + tg;
        sm[PP0 + qA*PST + kp]     = pack_bf16(u0 < p0 ? 1.0f : 0.0f,
                                              u1 < p1 ? 1.0f : 0.0f);
        sm[PP0 + (qA+8)*PST + kp] = pack_bf16(u2 < p2 ? 1.0f : 0.0f,
                                              u3 < p3 ? 1.0f : 0.0f);
      }
    }
    __syncthreads();

    // --- PV bf16x2: warp tile 32q x 32d (FULL d coverage) ---
#pragma unroll
    for (int c4 = 0; c4 < 2; c4++) {
      uint32_t a[2][4];
#pragma unroll
      for (int mt = 0; mt < 2; mt++) {
        const int row = wm2*32 + mt*16 + g;
        a[mt][0] = sm[PP0 + row    *PST + c4*8 + tg];
        a[mt][1] = sm[PP0 + (row+8)*PST + c4*8 + tg];
        a[mt][2] = sm[PP0 + row    *PST + c4*8 + tg + 4];
        a[mt][3] = sm[PP0 + (row+8)*PST + c4*8 + tg + 4];
      }
#pragma unroll
      for (int nt = 0; nt < 4; nt++) {
        const int d = wn2*32 + nt*8 + g;
        uint32_t bh0 = sm[VH0 + d*VST + c4*8 + tg];
        uint32_t bh1 = sm[VH0 + d*VST + c4*8 + tg + 4];
        uint32_t bl0 = sm[VH0 + 64*VST + d*VST + c4*8 + tg];
        uint32_t bl1 = sm[VH0 + 64*VST + d*VST + c4*8 + tg + 4];
#pragma unroll
        for (int mt = 0; mt < 2; mt++) {
          mma_bf16(co[mt][nt], a[mt], bh0, bh1);
          mma_bf16(co[mt][nt], a[mt], bl0, bl1);
        }
      }
    }
  }

  // Epilogue: pre-split AV (h/m) into [comp][kpair][row]
#pragma unroll
  for (int mt = 0; mt < 2; mt++) {
    const int q = q0 + wm2*32 + mt*16 + g;
    const int row = b*S_DIM + q;
#pragma unroll
    for (int nt = 0; nt < 4; nt++) {
      const int d = wn2*32 + nt*8 + tg*2;
      const int kpair = h*32 + (d >> 1);
      uint32_t hh, mm, ll;
      split3(co[mt][nt][0], co[mt][nt][1], hh, mm, ll);
      g_avp[(size_t)kpair*XROWS + row]       = hh;
      g_avp[AVC + (size_t)kpair*XROWS + row] = mm;
      split3(co[mt][nt][2], co[mt][nt][3], hh, mm, ll);
      g_avp[(size_t)kpair*XROWS + row + 8]       = hh;
      g_avp[AVC + (size_t)kpair*XROWS + row + 8] = mm;
    }
  }
}

// ===========================================================================
extern "C" void kernel_launch(void* const* d_in, const int* in_sizes, int n_in,
                              void* d_out, int out_size) {
  const float *x = nullptr, *qkv_w = nullptr, *qkv_b = nullptr;
  const float *out_w = nullptr, *out_b = nullptr;
  for (int i = 0; i < n_in; i++) {
    int sz = in_sizes[i];
    if (sz == B_DIM*S_DIM*E_DIM) { if (!x) x = (const float*)d_in[i]; }
    else if (sz == 3*E_DIM*E_DIM) qkv_w = (const float*)d_in[i];
    else if (sz == 3*E_DIM)       qkv_b = (const float*)d_in[i];
    else if (sz == E_DIM*E_DIM)   out_w = (const float*)d_in[i];
    else if (sz == E_DIM)         out_b = (const float*)d_in[i];
  }
  float* out = (float*)d_out;

  uint32_t *xp, *qwp, *owp, *avp;
  cudaGetSymbolAddress((void**)&xp,  g_xp);
  cudaGetSymbolAddress((void**)&qwp, g_qwp);
  cudaGetSymbolAddress((void**)&owp, g_owp);
  cudaGetSymbolAddress((void**)&avp, g_avp);

  // 0) pre-split static operands
  presplit<3><<<dim3(XROWS/256, KPAIRS), 256>>>(x, xp, XROWS);
  presplit<3><<<dim3(3*E_DIM/256, KPAIRS), 256>>>(qkv_w, qwp, 3*E_DIM);
  presplit<2><<<dim3(E_DIM/256, KPAIRS), 256>>>(out_w, owp, E_DIM);

  // 1) QKV from pre-split operands
  qkv_tc<1><<<dim3(32, 32), 256>>>(xp, qwp, qkv_b, 0);
  qkv_tc<0><<<dim3(16, 32), 256>>>(xp, qwp, qkv_b, 2048);

  // 2) fused attention (q-tile 64, 128 threads, 4 CTAs/SM)
  cudaFuncSetAttribute(attn_kernel, cudaFuncAttributeMaxDynamicSharedMemorySize,
                       ATTN_SMEM);
  attn_kernel<<<dim3(S_DIM/64, B_DIM*H_DIM), 128, ATTN_SMEM>>>();

  // 3) out = AV @ out_w^T + out_b
  bf16_proj<<<dim3(E_DIM/128, (B_DIM*S_DIM)/128), 256>>>(avp, owp, out_b, out);
}